// round 14
// baseline (speedup 1.0000x reference)
#include <cuda_runtime.h>

#define NRAD  16
#define NL    2
#define NOUT  144            // 16*(1 + 2*4)
#define L35   35
#define KG    9              // 9 chunks of 4 k-values (36 padded)
#define HALFT 144            // threads per atom: 16 j x 9 kg
#define BLOCK 288            // 2 atoms per block -> 9 full warps
#define MAXE   100000
#define MAXNAT 4096
#define PEDGE 32             // edges per prep block

__device__ int    g_segstart[MAXNAT + 1];
__device__ float4 g_gT[KG * MAXE];      // [kg][e]: 4 monomials, k=35 padded 0
__device__ float4 g_radT[MAXE * NRAD];  // [e][j]: channels 0..3 (16B aligned)
__device__ float  g_rad4[MAXE * NRAD];  // [e][j]: channel 4 (two-body)

typedef unsigned long long ull;

__device__ __forceinline__ ull pack2(float x, float y) {
    ull r; asm("mov.b64 %0, {%1, %2};" : "=l"(r) : "f"(x), "f"(y)); return r;
}
__device__ __forceinline__ ull dup2(float x) {
    ull r; asm("mov.b64 %0, {%1, %1};" : "=l"(r) : "f"(x)); return r;
}
__device__ __forceinline__ void unpack2(ull p, float& x, float& y) {
    asm("mov.b64 {%0, %1}, %2;" : "=f"(x), "=f"(y) : "l"(p));
}
__device__ __forceinline__ void fma2(ull& d, ull a, ull b) {
    asm("fma.rn.f32x2 %0, %1, %2, %0;" : "+l"(d) : "l"(a), "l"(b));
}

__constant__ int c_S[L35] = {0, 1,1,1, 2,2,2,2,2,2,
                             3,3,3,3,3,3,3,3,3,3,
                             4,4,4,4,4,4,4,4,4,4,4,4,4,4,4};

// Prepass: transpose radial to 16B-aligned layouts, monomials, segstarts.
__global__ __launch_bounds__(256)
void prep_kernel(const float* __restrict__ rij,
                 const float* __restrict__ radial,   // [E,16,5]
                 const int*   __restrict__ fidx,
                 int E, int nat)
{
    __shared__ float s_row[PEDGE * 80];     // 32 edges x 80 floats (10 KB)

    const int tid = threadIdx.x;
    const int e0  = blockIdx.x * PEDGE;
    const int cnt = min(PEDGE, E - e0);

    // coalesced load of 32 radial rows
    const float4* src = (const float4*)(radial + (size_t)e0 * 80);
    for (int i = tid; i < cnt * 20; i += 256)
        ((float4*)s_row)[i] = src[i];
    __syncthreads();

    // transposed writes: radT (ch0-3, aligned float4) and rad4 (ch4)
    for (int i = tid; i < cnt * NRAD; i += 256) {
        int e = i >> 4, j = i & 15;
        const float* p = &s_row[e*80 + j*5];
        g_radT[(size_t)(e0 + e) * NRAD + j] = make_float4(p[0], p[1], p[2], p[3]);
        g_rad4[(size_t)(e0 + e) * NRAD + j] = p[4];
    }

    // monomials + segstart: one thread per edge
    if (tid < cnt) {
        int e = e0 + tid;

        int cur  = fidx[e];
        int prev = (e == 0) ? -1 : fidx[e - 1];
        for (int a = prev + 1; a <= cur; a++) g_segstart[a] = e;
        if (e == E - 1)
            for (int a = cur + 1; a <= nat; a++) g_segstart[a] = E;

        constexpr int LXc[L35] = {0, 0,0,1, 0,0,0,1,1,2,
                                  0,0,0,0,1,1,1,2,2,3,
                                  0,0,0,0,0,1,1,1,1,2,2,2,3,3,4};
        constexpr int LYc[L35] = {0, 0,1,0, 0,1,2,0,1,0,
                                  0,1,2,3,0,1,2,0,1,0,
                                  0,1,2,3,4,0,1,2,3,0,1,2,0,1,0};
        constexpr int LZc[L35] = {0, 1,0,0, 2,1,0,1,0,0,
                                  3,2,1,0,2,1,0,1,0,0,
                                  4,3,2,1,0,3,2,1,0,2,1,0,1,0,0};
        constexpr float FNc[L35] = {1.f, 1.f,1.f,1.f,
                                    1.f,2.f,1.f,2.f,2.f,1.f,
                                    1.f,3.f,3.f,1.f,3.f,6.f,3.f,3.f,3.f,1.f,
                                    1.f,4.f,6.f,4.f,1.f,4.f,12.f,12.f,4.f,
                                    6.f,12.f,6.f,4.f,4.f,1.f};
        float x = rij[e*3+0], y = rij[e*3+1], z = rij[e*3+2];
        float px[5], py[5], pz[5];
        px[0]=1.f; px[1]=x; px[2]=x*x; px[3]=px[2]*x; px[4]=px[2]*px[2];
        py[0]=1.f; py[1]=y; py[2]=y*y; py[3]=py[2]*y; py[4]=py[2]*py[2];
        pz[0]=1.f; pz[1]=z; pz[2]=z*z; pz[3]=pz[2]*z; pz[4]=pz[2]*pz[2];
        float g[36];
        #pragma unroll
        for (int k = 0; k < L35; k++)
            g[k] = FNc[k] * px[LXc[k]] * py[LYc[k]] * pz[LZc[k]];
        g[35] = 0.f;
        #pragma unroll
        for (int kg = 0; kg < KG; kg++)   // consecutive e per kg -> coalesced
            g_gT[(size_t)kg * MAXE + e] =
                make_float4(g[kg*4+0], g[kg*4+1], g[kg*4+2], g[kg*4+3]);
    }
}

__global__ __launch_bounds__(BLOCK, 4)
void mbp_main(const float* __restrict__ lamw,     // [NL]
              float* __restrict__ out,            // [nat, NOUT]
              int nat)
{
    __shared__ float s_lam[NL][36];
    __shared__ float s_part[2][KG][NRAD][8];

    const int tid  = threadIdx.x;
    const int half = (tid >= HALFT) ? 1 : 0;
    const int t    = tid - half * HALFT;
    const int j    = t & 15;        // 0..15 radial index
    const int kg   = t >> 4;        // 0..8  angular chunk
    const int a    = blockIdx.x * 2 + half;

    if (tid < NL * 36) {
        int l = (tid >= 36) ? 1 : 0;
        int k = tid - l * 36;
        float p = 0.f;
        if (k < L35) {
            float b = lamw[l];
            int   s = c_S[k];
            p = 1.f;                       // exact integer power (b may be < 0)
            for (int i = 0; i < s; i++) p *= b;
        }
        s_lam[l][k] = p;
    }
    const int start = (a < nat) ? g_segstart[a]     : 0;
    const int end   = (a < nat) ? g_segstart[a + 1] : 0;
    __syncthreads();

    // accA[q] = (ch0,ch1) at k=k0+q ; accB[q] = (ch2,ch3)
    ull accA[4] = {0,0,0,0};
    ull accB[4] = {0,0,0,0};
    float accR = 0.f;

    const float4* rp = g_radT + (size_t)start * NRAD + j;
    const float4* gp = g_gT   + (size_t)kg * MAXE + start;
    const float*  cp = g_rad4 + (size_t)start * NRAD + j;

    #pragma unroll 8
    for (int e = start; e < end; e++) {
        float4 r4 = *rp;  rp += NRAD;
        float4 g4 = *gp++;
        if (kg == 0) accR += *cp;
        cp += NRAD;
        ull rA = pack2(r4.x, r4.y);        // (ch0,ch1)
        ull rB = pack2(r4.z, r4.w);        // (ch2,ch3)
        ull g0 = dup2(g4.x), g1 = dup2(g4.y), g2 = dup2(g4.z), g3 = dup2(g4.w);
        fma2(accA[0], rA, g0);  fma2(accB[0], rB, g0);
        fma2(accA[1], rA, g1);  fma2(accB[1], rB, g1);
        fma2(accA[2], rA, g2);  fma2(accB[2], rB, g2);
        fma2(accA[3], rA, g3);  fma2(accB[3], rB, g3);
    }

    // per-thread partial lambda contraction over this thread's 4 k-values
    {
        float lv0[4], lv1[4];
        #pragma unroll
        for (int q = 0; q < 4; q++) {
            lv0[q] = s_lam[0][kg*4 + q];
            lv1[q] = s_lam[1][kg*4 + q];
        }
        float sq[4][4];                    // [c][q]
        #pragma unroll
        for (int q = 0; q < 4; q++) {
            float u, v;
            unpack2(accA[q], u, v);  sq[0][q] = u*u;  sq[1][q] = v*v;
            unpack2(accB[q], u, v);  sq[2][q] = u*u;  sq[3][q] = v*v;
        }
        #pragma unroll
        for (int c = 0; c < 4; c++) {
            float p0 = fmaf(sq[c][0], lv0[0], fmaf(sq[c][1], lv0[1],
                       fmaf(sq[c][2], lv0[2], sq[c][3]*lv0[3])));
            float p1 = fmaf(sq[c][0], lv1[0], fmaf(sq[c][1], lv1[1],
                       fmaf(sq[c][2], lv1[2], sq[c][3]*lv1[3])));
            s_part[half][kg][j][c*2 + 0] = p0;
            s_part[half][kg][j][c*2 + 1] = p1;
        }
    }
    if (kg == 0 && a < nat) out[(size_t)a * NOUT + j] = accR;
    __syncthreads();

    // reduce over kg groups: 256 outputs = 2 atoms x (j2, c, l)
    if (tid < 256) {
        int h2  = tid >> 7;          // atom half
        int low = tid & 127;
        int co  = low & 7;           // c*2 + l
        int j2  = low >> 3;          // 0..15
        int ao  = blockIdx.x * 2 + h2;
        if (ao < nat) {
            float sum = 0.f;
            #pragma unroll
            for (int k = 0; k < KG; k++) sum += s_part[h2][k][j2][co];
            int c = co >> 1, l = co & 1;
            float scale = __int_as_float(0x3F800000 - (c << 23));   // 2^-c
            out[(size_t)ao * NOUT + NRAD + c*(NRAD*NL) + j2*NL + l] = sum * scale;
        }
    }
}

extern "C" void kernel_launch(void* const* d_in, const int* in_sizes, int n_in,
                              void* d_out, int out_size)
{
    const float* rij    = (const float*)d_in[0];   // [E,3]
    const float* radial = (const float*)d_in[1];   // [E,16,5]
    const float* lamw   = (const float*)d_in[2];   // [2]
    const int*   fidx   = (const int*)  d_in[4];   // [E] sorted

    const int E   = in_sizes[0] / 3;
    const int nat = out_size / NOUT;

    prep_kernel<<<(E + PEDGE - 1) / PEDGE, 256>>>(rij, radial, fidx, E, nat);
    mbp_main  <<<(nat + 1) / 2, BLOCK>>>(lamw, (float*)d_out, nat);
}

// round 15
// speedup vs baseline: 1.3163x; 1.3163x over previous
#include <cuda_runtime.h>

#define NRAD  16
#define NL    2
#define NOUT  144            // 16*(1 + 2*4)
#define L35   35
#define KG    9              // 9 chunks of 4 k-values (36 padded)
#define HALFT 144            // threads per atom: 16 j x 9 kg
#define BLOCK 288            // 2 atoms per block -> 9 full warps
#define MAXE   100000
#define MAXNAT 4096

__device__ int    g_segstart[MAXNAT + 1];
__device__ float4 g_gT[KG * MAXE];      // [kg][e]: 4 monomials, k=35 padded to 0

typedef unsigned long long ull;

__device__ __forceinline__ ull pack2(float x, float y) {
    ull r; asm("mov.b64 %0, {%1, %2};" : "=l"(r) : "f"(x), "f"(y)); return r;
}
__device__ __forceinline__ ull dup2(float x) {
    ull r; asm("mov.b64 %0, {%1, %1};" : "=l"(r) : "f"(x)); return r;
}
__device__ __forceinline__ void unpack2(ull p, float& x, float& y) {
    asm("mov.b64 {%0, %1}, %2;" : "=f"(x), "=f"(y) : "l"(p));
}
__device__ __forceinline__ void fma2(ull& d, ull a, ull b) {
    asm("fma.rn.f32x2 %0, %1, %2, %0;" : "+l"(d) : "l"(a), "l"(b));
}

__constant__ int c_S[L35] = {0, 1,1,1, 2,2,2,2,2,2,
                             3,3,3,3,3,3,3,3,3,3,
                             4,4,4,4,4,4,4,4,4,4,4,4,4,4,4};

// Compile-time monomial tables (padded slot 35 -> FN 0)
template<int KGI>
__device__ __forceinline__ float4 mono4(float x, float y, float z)
{
    constexpr int LX[36] = {0, 0,0,1, 0,0,0,1,1,2,
                            0,0,0,0,1,1,1,2,2,3,
                            0,0,0,0,0,1,1,1,1,2,2,2,3,3,4, 0};
    constexpr int LY[36] = {0, 0,1,0, 0,1,2,0,1,0,
                            0,1,2,3,0,1,2,0,1,0,
                            0,1,2,3,4,0,1,2,3,0,1,2,0,1,0, 0};
    constexpr int LZ[36] = {0, 1,0,0, 2,1,0,1,0,0,
                            3,2,1,0,2,1,0,1,0,0,
                            4,3,2,1,0,3,2,1,0,2,1,0,1,0,0, 0};
    constexpr float FN[36] = {1.f, 1.f,1.f,1.f,
                              1.f,2.f,1.f,2.f,2.f,1.f,
                              1.f,3.f,3.f,1.f,3.f,6.f,3.f,3.f,3.f,1.f,
                              1.f,4.f,6.f,4.f,1.f,4.f,12.f,12.f,4.f,
                              6.f,12.f,6.f,4.f,4.f,1.f, 0.f};
    float px[5], py[5], pz[5];
    px[0]=1.f; px[1]=x; px[2]=x*x; px[3]=px[2]*x; px[4]=px[2]*px[2];
    py[0]=1.f; py[1]=y; py[2]=y*y; py[3]=py[2]*y; py[4]=py[2]*py[2];
    pz[0]=1.f; pz[1]=z; pz[2]=z*z; pz[3]=pz[2]*z; pz[4]=pz[2]*pz[2];
    float4 m;
    m.x = FN[KGI*4+0] * px[LX[KGI*4+0]] * py[LY[KGI*4+0]] * pz[LZ[KGI*4+0]];
    m.y = FN[KGI*4+1] * px[LX[KGI*4+1]] * py[LY[KGI*4+1]] * pz[LZ[KGI*4+1]];
    m.z = FN[KGI*4+2] * px[LX[KGI*4+2]] * py[LY[KGI*4+2]] * pz[LZ[KGI*4+2]];
    m.w = FN[KGI*4+3] * px[LX[KGI*4+3]] * py[LY[KGI*4+3]] * pz[LZ[KGI*4+3]];
    return m;
}

// Prep v2: 2D grid (E/256, 9). One thread per (edge, kg-chunk).
// kg plane 0 also computes segment starts. ~3500 blocks -> full occupancy.
__global__ __launch_bounds__(256)
void prep_kernel(const float* __restrict__ rij, const int* __restrict__ fidx,
                 int E, int nat)
{
    const int e  = blockIdx.x * 256 + threadIdx.x;
    const int kg = blockIdx.y;
    if (e >= E) return;

    if (kg == 0) {
        int cur  = __ldg(&fidx[e]);
        int prev = (e == 0) ? -1 : __ldg(&fidx[e - 1]);
        for (int a = prev + 1; a <= cur; a++) g_segstart[a] = e;
        if (e == E - 1)
            for (int a = cur + 1; a <= nat; a++) g_segstart[a] = E;
    }

    float x = __ldg(&rij[e*3+0]);
    float y = __ldg(&rij[e*3+1]);
    float z = __ldg(&rij[e*3+2]);

    float4 m;
    switch (kg) {
        case 0: m = mono4<0>(x, y, z); break;
        case 1: m = mono4<1>(x, y, z); break;
        case 2: m = mono4<2>(x, y, z); break;
        case 3: m = mono4<3>(x, y, z); break;
        case 4: m = mono4<4>(x, y, z); break;
        case 5: m = mono4<5>(x, y, z); break;
        case 6: m = mono4<6>(x, y, z); break;
        case 7: m = mono4<7>(x, y, z); break;
        default: m = mono4<8>(x, y, z); break;
    }
    g_gT[kg * MAXE + e] = m;
}

__global__ __launch_bounds__(BLOCK, 4)
void mbp_main(const float* __restrict__ radial,   // [E,16,5]
              const float* __restrict__ lamw,     // [NL]
              float* __restrict__ out,            // [nat, NOUT]
              int nat)
{
    __shared__ float s_lam[NL][36];
    __shared__ float s_part[2][KG][NRAD][8];

    const int tid  = threadIdx.x;
    const int half = (tid >= HALFT) ? 1 : 0;
    const int t    = tid - half * HALFT;
    const int j    = t & 15;        // 0..15 radial index
    const int kg   = t >> 4;        // 0..8  angular chunk
    const int a    = blockIdx.x * 2 + half;

    if (tid < NL * 36) {
        int l = (tid >= 36) ? 1 : 0;
        int k = tid - l * 36;
        float p = 0.f;
        if (k < L35) {
            float b = lamw[l];
            int   s = c_S[k];
            p = 1.f;                       // exact integer power (b may be < 0)
            for (int i = 0; i < s; i++) p *= b;
        }
        s_lam[l][k] = p;
    }
    const int start = (a < nat) ? g_segstart[a]     : 0;
    const int end   = (a < nat) ? g_segstart[a + 1] : 0;
    __syncthreads();

    ull acc0[4] = {0,0,0,0};        // (k0,k0+1) per channel
    ull acc1[4] = {0,0,0,0};        // (k0+2,k0+3) per channel
    float accR = 0.f;               // two-body channel (kg==0 only)

    const float*  rp = radial + (size_t)start * 80 + j * 5;
    const float4* gp = g_gT + (size_t)kg * MAXE + start;

    #pragma unroll 8
    for (int e = start; e < end; e++) {
        float4 g4 = *gp++;
        float r0 = rp[0], r1 = rp[1], r2 = rp[2], r3 = rp[3];
        if (kg == 0) accR += rp[4];
        rp += 80;
        ull gA = pack2(g4.x, g4.y);
        ull gB = pack2(g4.z, g4.w);
        ull d0 = dup2(r0), d1 = dup2(r1), d2 = dup2(r2), d3 = dup2(r3);
        fma2(acc0[0], gA, d0);  fma2(acc1[0], gB, d0);
        fma2(acc0[1], gA, d1);  fma2(acc1[1], gB, d1);
        fma2(acc0[2], gA, d2);  fma2(acc1[2], gB, d2);
        fma2(acc0[3], gA, d3);  fma2(acc1[3], gB, d3);
    }

    // per-thread partial lambda contraction over this thread's 4 k-values
    {
        float lv0[4], lv1[4];
        #pragma unroll
        for (int q = 0; q < 4; q++) {
            lv0[q] = s_lam[0][kg*4 + q];
            lv1[q] = s_lam[1][kg*4 + q];
        }
        #pragma unroll
        for (int c = 0; c < 4; c++) {
            float u, v, w, tt;
            unpack2(acc0[c], u, v);
            unpack2(acc1[c], w, tt);
            float s0 = u*u, s1 = v*v, s2 = w*w, s3 = tt*tt;
            float p0 = fmaf(s0, lv0[0], fmaf(s1, lv0[1], fmaf(s2, lv0[2], s3*lv0[3])));
            float p1 = fmaf(s0, lv1[0], fmaf(s1, lv1[1], fmaf(s2, lv1[2], s3*lv1[3])));
            s_part[half][kg][j][c*2 + 0] = p0;
            s_part[half][kg][j][c*2 + 1] = p1;
        }
    }
    if (kg == 0 && a < nat) out[(size_t)a * NOUT + j] = accR;
    __syncthreads();

    // reduce over kg groups: 256 outputs = 2 atoms x (j2, c, l)
    if (tid < 256) {
        int h2  = tid >> 7;          // atom half
        int low = tid & 127;
        int co  = low & 7;           // c*2 + l
        int j2  = low >> 3;          // 0..15
        int ao  = blockIdx.x * 2 + h2;
        if (ao < nat) {
            float sum = 0.f;
            #pragma unroll
            for (int k = 0; k < KG; k++) sum += s_part[h2][k][j2][co];
            int c = co >> 1, l = co & 1;
            float scale = __int_as_float(0x3F800000 - (c << 23));   // 2^-c
            out[(size_t)ao * NOUT + NRAD + c*(NRAD*NL) + j2*NL + l] = sum * scale;
        }
    }
}

extern "C" void kernel_launch(void* const* d_in, const int* in_sizes, int n_in,
                              void* d_out, int out_size)
{
    const float* rij    = (const float*)d_in[0];   // [E,3]
    const float* radial = (const float*)d_in[1];   // [E,16,5]
    const float* lamw   = (const float*)d_in[2];   // [2]
    const int*   fidx   = (const int*)  d_in[4];   // [E] sorted

    const int E   = in_sizes[0] / 3;
    const int nat = out_size / NOUT;

    dim3 pgrid((E + 255) / 256, KG);
    prep_kernel<<<pgrid, 256>>>(rij, fidx, E, nat);
    mbp_main  <<<(nat + 1) / 2, BLOCK>>>(radial, lamw, (float*)d_out, nat);
}